// round 12
// baseline (speedup 1.0000x reference)
#include <cuda_runtime.h>
#include <math.h>
#include <stdint.h>

#define BB   2
#define HH   16
#define TT   2048
#define DH   64
#define DD   1024
#define NC   12      // candidates carried into fp64 re-rank (k=8 + 4 margin)
#define JT   128     // key-columns per attention tile
#define QR   64      // query rows per attention CTA
#define KP   68      // smem row pitch in floats (64 + 4 pad, conflict-free)
#define ATHREADS 512

// -------- scratch (device globals; no allocation allowed) --------
__device__ float g_q[BB*HH*TT*DH];
__device__ float g_k[BB*HH*TT*DH];
__device__ float g_v[BB*HH*TT*DH];
__device__ float g_att[BB*TT*DD];

// ============================================================================
// SGEMM (NT): C[m][n] = sum_k A[m][k] * B[n][k]
// BM=BN=128, BK=16, 256 threads, 8x8 per thread. (Proven-fastest R10 variant,
// verbatim: single smem buffer, loads at loop top, two barriers, two-level
// accumulation every 32 k-steps to keep q/k within ~1e-7 of the reference.)
// A == nullptr  -> read A from the device-global g_att (out-proj input).
// scatter == 1  -> QKV projection: scatter into g_q/g_k/g_v, head-split layout.
// ============================================================================
__global__ __launch_bounds__(256)
void sgemm_nt(const float* __restrict__ A, const float* __restrict__ B,
              float* __restrict__ C, int M, int N, int K, int scatter)
{
    __shared__ float As[16][132];
    __shared__ float Bs[16][132];

    const float* Abase = A ? A : (const float*)g_att;

    const int tid = threadIdx.x;
    const int m0  = blockIdx.y * 128;
    const int n0  = blockIdx.x * 128;
    const int tx  = tid & 15;
    const int ty  = tid >> 4;
    const int lr  = tid >> 2;          // 0..63
    const int lc  = (tid & 3) << 2;    // 0,4,8,12

    float acc[8][8];
    float cacc[8][8];
    #pragma unroll
    for (int i = 0; i < 8; i++)
        #pragma unroll
        for (int j = 0; j < 8; j++) { acc[i][j] = 0.f; cacc[i][j] = 0.f; }

    const float* Ap = Abase + (size_t)(m0 + lr) * K + lc;
    const float* Bp = B     + (size_t)(n0 + lr) * K + lc;

    for (int k0 = 0; k0 < K; k0 += 16) {
        float4 a0 = *(const float4*)(Ap + k0);
        float4 a1 = *(const float4*)(Ap + (size_t)64 * K + k0);
        float4 b0 = *(const float4*)(Bp + k0);
        float4 b1 = *(const float4*)(Bp + (size_t)64 * K + k0);
        __syncthreads();
        As[lc+0][lr]    = a0.x; As[lc+1][lr]    = a0.y; As[lc+2][lr]    = a0.z; As[lc+3][lr]    = a0.w;
        As[lc+0][lr+64] = a1.x; As[lc+1][lr+64] = a1.y; As[lc+2][lr+64] = a1.z; As[lc+3][lr+64] = a1.w;
        Bs[lc+0][lr]    = b0.x; Bs[lc+1][lr]    = b0.y; Bs[lc+2][lr]    = b0.z; Bs[lc+3][lr]    = b0.w;
        Bs[lc+0][lr+64] = b1.x; Bs[lc+1][lr+64] = b1.y; Bs[lc+2][lr+64] = b1.z; Bs[lc+3][lr+64] = b1.w;
        __syncthreads();

        #pragma unroll
        for (int kk = 0; kk < 16; kk++) {
            float a[8], b[8];
            *(float4*)&a[0] = *(const float4*)&As[kk][ty*8];
            *(float4*)&a[4] = *(const float4*)&As[kk][ty*8 + 4];
            *(float4*)&b[0] = *(const float4*)&Bs[kk][tx*8];
            *(float4*)&b[4] = *(const float4*)&Bs[kk][tx*8 + 4];
            #pragma unroll
            for (int i = 0; i < 8; i++)
                #pragma unroll
                for (int j = 0; j < 8; j++)
                    cacc[i][j] = fmaf(a[i], b[j], cacc[i][j]);
        }

        if (k0 & 16) {   // flush every 32 k-steps (K % 32 == 0)
            #pragma unroll
            for (int i = 0; i < 8; i++)
                #pragma unroll
                for (int j = 0; j < 8; j++) { acc[i][j] += cacc[i][j]; cacc[i][j] = 0.f; }
        }
    }

    if (!scatter) {
        #pragma unroll
        for (int i = 0; i < 8; i++) {
            float* cp = C + (size_t)(m0 + ty*8 + i) * N + n0 + tx*8;
            *(float4*)cp       = make_float4(acc[i][0], acc[i][1], acc[i][2], acc[i][3]);
            *(float4*)(cp + 4) = make_float4(acc[i][4], acc[i][5], acc[i][6], acc[i][7]);
        }
    } else {
        #pragma unroll
        for (int i = 0; i < 8; i++) {
            int t  = m0 + ty*8 + i;
            int b_ = t >> 11;          // /2048
            int tl = t & 2047;
            #pragma unroll
            for (int j = 0; j < 8; j++) {
                int o    = n0 + tx*8 + j;
                int part = o >> 10;        // 0=q 1=k 2=v
                int rem  = o & 1023;
                int h    = rem >> 6;
                int dhi  = rem & 63;
                float* dst = (part == 0) ? g_q : (part == 1) ? g_k : g_v;
                dst[(((size_t)(b_*HH + h)) * TT + tl) * DH + dhi] = acc[i][j];
            }
        }
    }
}

// ============================================================================
// Fused causal scores + streaming top-k + fp64 re-rank + softmax + sparse AV.
// v3: 512 threads (16 warps = 4/SMSP for latency hiding), 64 query rows/CTA,
// cp.async double-buffered 128-col K tiles (no register staging), and the
// column index PACKED into the low 11 mantissa bits of the fp32 score
// (tv+ti 64 regs -> tv 32 regs; packed values are unique so merge needs no
// tie-break and no index shuffle). The <=1.5e-3 packing perturbation only
// affects candidate filtering; the fp64 exact re-rank still decides the final
// top-8 (NC=12 margin makes containment failure probability negligible).
// Grid: (32 = B*H, 32 = T/64). Q pre-scaled by 1/8 at load (exact).
// ============================================================================
__device__ __forceinline__ void cp16(unsigned saddr, const void* gptr)
{
    asm volatile("cp.async.cg.shared.global [%0], [%1], 16;\n" :: "r"(saddr), "l"(gptr));
}

__global__ __launch_bounds__(ATHREADS)
void attn_topk_kernel()
{
    extern __shared__ float sm[];
    // layout: ks0[JT*KP] | ks1[JT*KP] | qs[QR*KP]
    float* const ks0 = sm;
    float* const ks1 = sm + JT * KP;
    float* const qs  = sm + 2 * JT * KP;

    const int bh   = blockIdx.x;
    const int qt   = (int)gridDim.y - 1 - (int)blockIdx.y;  // heavy tiles first
    const int row0 = qt * QR;
    const int tid  = threadIdx.x;
    const int wid  = tid >> 5;
    const int lane = tid & 31;

    const float* Qb = g_q + (size_t)bh * TT * DH;
    const float* Kb = g_k + (size_t)bh * TT * DH;
    const float* Vb = g_v + (size_t)bh * TT * DH;

    const int ntiles = (row0 + QR + JT - 1) / JT;

    // prologue: cp.async K tile 0 into ks0 (4 x 16B per thread)
    #pragma unroll
    for (int i = 0; i < 4; i++) {
        int ii = tid + ATHREADS * i;
        int r = ii >> 4, c = (ii & 15) << 2;
        cp16((unsigned)__cvta_generic_to_shared(&ks0[r * KP + c]),
             Kb + (size_t)r * DH + c);
    }
    asm volatile("cp.async.commit_group;\n");

    // load Q tile (64 rows x 64), scaled by 1/8 (power of two: exact)
    #pragma unroll
    for (int i = 0; i < 2; i++) {
        int idx = tid + ATHREADS * i;
        int r = idx >> 4, c = (idx & 15) << 2;
        float4 v = *(const float4*)(Qb + (size_t)(row0 + r) * DH + c);
        v.x *= 0.125f; v.y *= 0.125f; v.z *= 0.125f; v.w *= 0.125f;
        *(float4*)&qs[r * KP + c] = v;
    }

    const int rbase = wid * 4;          // wid 0..15 -> rows 0..63
    const int g0    = row0 + rbase;

    const float SENT = __uint_as_float(0xFF000000u);   // ~ -1.70e38, idx bits 0
    float tv[4][8];
    #pragma unroll
    for (int r = 0; r < 4; r++)
        #pragma unroll
        for (int p = 0; p < 8; p++) tv[r][p] = SENT;

    for (int tj = 0; tj < ntiles; tj++) {
        const int j0 = tj * JT;
        float* kb = (tj & 1) ? ks1 : ks0;

        if (tj + 1 < ntiles) {
            float* nb = (tj & 1) ? ks0 : ks1;
            const int jn = (tj + 1) * JT;
            #pragma unroll
            for (int i = 0; i < 4; i++) {
                int ii = tid + ATHREADS * i;
                int r = ii >> 4, c = (ii & 15) << 2;
                cp16((unsigned)__cvta_generic_to_shared(&nb[r * KP + c]),
                     Kb + (size_t)(jn + r) * DH + c);
            }
            asm volatile("cp.async.commit_group;\n");
            asm volatile("cp.async.wait_group 1;\n");   // tile tj complete
        } else {
            asm volatile("cp.async.wait_group 0;\n");
        }
        __syncthreads();

        float s[4][4];
        #pragma unroll
        for (int r = 0; r < 4; r++)
            #pragma unroll
            for (int c = 0; c < 4; c++) s[r][c] = 0.f;

        #pragma unroll
        for (int d = 0; d < 16; d++) {
            float4 k0 = *(const float4*)(kb + (lane      ) * KP + 4 * d);
            float4 k1 = *(const float4*)(kb + (lane + 32 ) * KP + 4 * d);
            float4 k2 = *(const float4*)(kb + (lane + 64 ) * KP + 4 * d);
            float4 k3 = *(const float4*)(kb + (lane + 96 ) * KP + 4 * d);
            #pragma unroll
            for (int r = 0; r < 4; r++) {
                float4 q = *(const float4*)(qs + (rbase + r) * KP + 4 * d);
                s[r][0] = fmaf(q.w, k0.w, fmaf(q.z, k0.z, fmaf(q.y, k0.y, fmaf(q.x, k0.x, s[r][0]))));
                s[r][1] = fmaf(q.w, k1.w, fmaf(q.z, k1.z, fmaf(q.y, k1.y, fmaf(q.x, k1.x, s[r][1]))));
                s[r][2] = fmaf(q.w, k2.w, fmaf(q.z, k2.z, fmaf(q.y, k2.y, fmaf(q.x, k2.x, s[r][2]))));
                s[r][3] = fmaf(q.w, k3.w, fmaf(q.z, k3.z, fmaf(q.y, k3.y, fmaf(q.x, k3.x, s[r][3]))));
            }
        }

        // topk update: pack index into low 11 mantissa bits, insert if in top-8
        #pragma unroll
        for (int r = 0; r < 4; r++) {
            const int gi = g0 + r;
            #pragma unroll
            for (int c = 0; c < 4; c++) {
                int j = j0 + c * 32 + lane;
                if (j <= gi) {
                    unsigned u = (__float_as_uint(s[r][c]) & 0xFFFFF800u) | (unsigned)j;
                    float pf = __uint_as_float(u);
                    if (pf > tv[r][7]) {
                        float cv = pf;
                        #pragma unroll
                        for (int p = 0; p < 8; p++) {
                            if (cv > tv[r][p]) { float t = tv[r][p]; tv[r][p] = cv; cv = t; }
                        }
                    }
                }
            }
        }
        __syncthreads();   // all warps done with kb before it is overwritten
    }

    const int b_ = bh >> 4;
    const int h  = bh & 15;

    #pragma unroll
    for (int r = 0; r < 4; r++) {
        int gi = g0 + r;

        // ---- merge lane-local top-8 -> global top-NC candidate indices ----
        // packed values are unique (index embedded), so exactly one owner.
        int mi[NC];
        #pragma unroll
        for (int n = 0; n < NC; n++) {
            float head = tv[r][0];
            float best = head;
            #pragma unroll
            for (int off = 16; off > 0; off >>= 1)
                best = fmaxf(best, __shfl_xor_sync(0xffffffffu, best, off));
            if (best < -1.0e37f) {        // uniform across warp
                mi[n] = -1;
            } else {
                mi[n] = (int)(__float_as_uint(best) & 2047u);
                unsigned bal = __ballot_sync(0xffffffffu, head == best);
                int owner = __ffs((int)bal) - 1;
                if (lane == owner) {
                    #pragma unroll
                    for (int p = 0; p < 7; p++) tv[r][p] = tv[r][p + 1];
                    tv[r][7] = SENT;
                }
            }
        }

        // ---- fp64 exact recompute of candidate scores (warp-cooperative) ----
        // qs holds q/8 (exact scaling), so the dot is the exact scaled score.
        const float* qrow = qs + (rbase + r) * KP;
        float q1 = qrow[lane];
        float q2 = qrow[lane + 32];
        double dv[NC];
        #pragma unroll
        for (int n = 0; n < NC; n++) {
            int j = mi[n];
            double p = 0.0;
            if (j >= 0) {
                const float* kr = Kb + (size_t)j * DH;
                p = (double)q1 * (double)kr[lane] + (double)q2 * (double)kr[lane + 32];
            }
            #pragma unroll
            for (int off = 16; off > 0; off >>= 1)
                p += __shfl_xor_sync(0xffffffffu, p, off);
            dv[n] = (j >= 0) ? p : -1.0e300;
        }

        // ---- select top keff by fp64 rank; softmax; sparse AV ----
        int keff = min(gi + 1, 8);
        double mx = dv[0];
        #pragma unroll
        for (int n = 1; n < NC; n++) if (dv[n] > mx) mx = dv[n];

        float w[NC];
        float den = 0.f;
        #pragma unroll
        for (int n = 0; n < NC; n++) {
            int rank = 0;
            #pragma unroll
            for (int m = 0; m < NC; m++) rank += (dv[m] > dv[n]) ? 1 : 0;
            bool keep = (mi[n] >= 0) && (rank < keff);
            float wn = keep ? __expf((float)(dv[n] - mx)) : 0.f;
            w[n] = wn;
            den += wn;
        }

        float o0 = 0.f, o1 = 0.f;
        #pragma unroll
        for (int n = 0; n < NC; n++) {
            if (w[n] > 0.f) {   // uniform across warp (mi, dv identical on all lanes)
                const float* vr = Vb + (size_t)mi[n] * DH;
                o0 = fmaf(w[n], vr[lane],      o0);
                o1 = fmaf(w[n], vr[lane + 32], o1);
            }
        }
        float inv = 1.f / den;
        float* op = g_att + ((size_t)b_ * TT + gi) * DD + h * DH;
        op[lane]      = o0 * inv;
        op[lane + 32] = o1 * inv;
    }
}

// ============================================================================
// launch — kernel launches only (plus one idempotent, non-stream attribute
// call for the >48KB dynamic smem opt-in; legal under graph capture).
// ============================================================================
extern "C" void kernel_launch(void* const* d_in, const int* in_sizes, int n_in,
                              void* d_out, int out_size)
{
    const float* x     = (const float*)d_in[0];   // (2,2048,1024)
    const float* w_qkv = (const float*)d_in[1];   // (3072,1024)
    const float* w_out = (const float*)d_in[2];   // (1024,1024)
    float* out = (float*)d_out;                   // (2,2048,1024)

    const int ATTN_SMEM = (2 * JT * KP + QR * KP) * (int)sizeof(float);  // 87040 B
    cudaFuncSetAttribute(attn_topk_kernel,
                         cudaFuncAttributeMaxDynamicSharedMemorySize, ATTN_SMEM);

    dim3 blk(256);
    // QKV projection + head-split scatter: M=4096, N=3072, K=1024
    sgemm_nt<<<dim3(3072 / 128, 4096 / 128), blk>>>(x, w_qkv, nullptr, 4096, 3072, 1024, 1);
    // fused causal scores + top-k + fp64 re-rank + softmax + sparse AV
    attn_topk_kernel<<<dim3(BB * HH, TT / QR), ATHREADS, ATTN_SMEM>>>();
    // output projection: M=4096, N=1024, K=1024  (A = g_att via nullptr)
    sgemm_nt<<<dim3(1024 / 128, 4096 / 128), blk>>>(nullptr, w_out, out, 4096, 1024, 1024, 0);
}